// round 3
// baseline (speedup 1.0000x reference)
#include <cuda_runtime.h>
#include <cstdint>

// AcousticPhysicsEngine: out[idx_row[i]] += vals[i] * field.T.flat[idx_col[i]]
// field: [256,256] f32 (256KB, kept L1-resident); idx_*: int32; out: [131072] f32.
// Strategy: streaming inputs use __ldcs (evict-first) so L1 caches only the
// gather target; scatters are RED.ADD.F32 (atomicAdd with unused result).

__global__ void zero_out_kernel(float* __restrict__ out, int n) {
    int i = blockIdx.x * blockDim.x + threadIdx.x;
    if (i < n) out[i] = 0.0f;
}

__device__ __forceinline__ float gather_field(const float* __restrict__ field, unsigned c) {
    // column-major flatten: flat[c] = field[(c % 256) * 256 + (c / 256)]
    return __ldg(field + (((c & 255u) << 8) | (c >> 8)));
}

__global__ void __launch_bounds__(256)
spmv_scatter_kernel(const float* __restrict__ field,
                    const int*   __restrict__ idx_row,
                    const int*   __restrict__ idx_col,
                    const float* __restrict__ vals,
                    float*       __restrict__ out,
                    long long nnz)
{
    // 8 nonzeros per thread, direct (non-grid-stride) mapping.
    long long g = (long long)blockIdx.x * blockDim.x + threadIdx.x;
    long long base = g << 3;

    if (base + 8 <= nnz) {
        // Front-batched streaming loads (evict-first: don't pollute L1).
        int4   c0 = __ldcs(reinterpret_cast<const int4*>(idx_col + base));
        int4   c1 = __ldcs(reinterpret_cast<const int4*>(idx_col + base + 4));
        int4   r0 = __ldcs(reinterpret_cast<const int4*>(idx_row + base));
        int4   r1 = __ldcs(reinterpret_cast<const int4*>(idx_row + base + 4));
        float4 v0 = __ldcs(reinterpret_cast<const float4*>(vals + base));
        float4 v1 = __ldcs(reinterpret_cast<const float4*>(vals + base + 4));

        float f0 = gather_field(field, (unsigned)c0.x);
        float f1 = gather_field(field, (unsigned)c0.y);
        float f2 = gather_field(field, (unsigned)c0.z);
        float f3 = gather_field(field, (unsigned)c0.w);
        float f4 = gather_field(field, (unsigned)c1.x);
        float f5 = gather_field(field, (unsigned)c1.y);
        float f6 = gather_field(field, (unsigned)c1.z);
        float f7 = gather_field(field, (unsigned)c1.w);

        atomicAdd(out + (unsigned)r0.x, v0.x * f0);
        atomicAdd(out + (unsigned)r0.y, v0.y * f1);
        atomicAdd(out + (unsigned)r0.z, v0.z * f2);
        atomicAdd(out + (unsigned)r0.w, v0.w * f3);
        atomicAdd(out + (unsigned)r1.x, v1.x * f4);
        atomicAdd(out + (unsigned)r1.y, v1.y * f5);
        atomicAdd(out + (unsigned)r1.z, v1.z * f6);
        atomicAdd(out + (unsigned)r1.w, v1.w * f7);
    } else if (base < nnz) {
        // Tail: scalar
        for (long long i = base; i < nnz; i++) {
            unsigned cc = (unsigned)__ldcs(idx_col + i);
            float f = gather_field(field, cc);
            atomicAdd(out + (unsigned)__ldcs(idx_row + i), __ldcs(vals + i) * f);
        }
    }
}

extern "C" void kernel_launch(void* const* d_in, const int* in_sizes, int n_in,
                              void* d_out, int out_size)
{
    const float* field   = (const float*)d_in[0];  // [65536]
    const int*   idx_row = (const int*)d_in[1];    // [NNZ] int32
    const int*   idx_col = (const int*)d_in[2];    // [NNZ] int32
    const float* vals    = (const float*)d_in[3];  // [NNZ]
    float* out = (float*)d_out;                    // [131072]
    long long nnz = (long long)in_sizes[1];

    {
        int threads = 256;
        int blocks = (out_size + threads - 1) / threads;
        zero_out_kernel<<<blocks, threads>>>(out, out_size);
    }
    {
        int threads = 256;
        long long ngroups = (nnz + 7) >> 3;                 // 8 nnz per thread
        int blocks = (int)((ngroups + threads - 1) / threads);
        spmv_scatter_kernel<<<blocks, threads>>>(field, idx_row, idx_col, vals, out, nnz);
    }
}

// round 5
// speedup vs baseline: 1.3109x; 1.3109x over previous
#include <cuda_runtime.h>
#include <cstdint>

// out[idx_row[i]] += vals[i] * field[rm(idx_col[i])],  rm(c) = ((c&255)<<8)|(c>>8)
// field: 256KB. Strategy: keep first 227KB of field (row-major) in SMEM,
// gather via LDS (random ~4cyc/warp) instead of divergent L1tex wavefronts;
// remaining 11.3% of gathers fall back to L2 via __ldg. Streams are __ldcs.

#define SMEM_BYTES  232448           // 227 KB max dynamic smem on sm_103
#define SMEM_FLOATS (SMEM_BYTES / 4) // 58112

__global__ void zero_out_kernel(float* __restrict__ out, int n) {
    int i = blockIdx.x * blockDim.x + threadIdx.x;
    if (i < n) out[i] = 0.0f;
}

__global__ void __launch_bounds__(1024, 1)
spmv_smem_kernel(const float* __restrict__ field,
                 const int*   __restrict__ idx_row,
                 const int*   __restrict__ idx_col,
                 const float* __restrict__ vals,
                 float*       __restrict__ out,
                 long long nnz)
{
    extern __shared__ float s_field[];

    // Coalesced fill: row-major copy of field[0:SMEM_FLOATS]
    {
        const float4* f4 = reinterpret_cast<const float4*>(field);
        float4* s4 = reinterpret_cast<float4*>(s_field);
        for (int i = threadIdx.x; i < SMEM_FLOATS / 4; i += blockDim.x)
            s4[i] = f4[i];
    }
    __syncthreads();

    long long tid    = (long long)blockIdx.x * blockDim.x + threadIdx.x;
    long long stride = (long long)gridDim.x * blockDim.x;

    long long nvec = nnz >> 2;
    for (long long g = tid; g < nvec; g += stride) {
        long long base = g << 2;

        int4   c = __ldcs(reinterpret_cast<const int4*>(idx_col + base));
        int4   r = __ldcs(reinterpret_cast<const int4*>(idx_row + base));
        float4 v = __ldcs(reinterpret_cast<const float4*>(vals + base));

        unsigned rm0 = (((unsigned)c.x & 255u) << 8) | ((unsigned)c.x >> 8);
        unsigned rm1 = (((unsigned)c.y & 255u) << 8) | ((unsigned)c.y >> 8);
        unsigned rm2 = (((unsigned)c.z & 255u) << 8) | ((unsigned)c.z >> 8);
        unsigned rm3 = (((unsigned)c.w & 255u) << 8) | ((unsigned)c.w >> 8);

        float f0 = (rm0 < SMEM_FLOATS) ? s_field[rm0] : __ldg(field + rm0);
        float f1 = (rm1 < SMEM_FLOATS) ? s_field[rm1] : __ldg(field + rm1);
        float f2 = (rm2 < SMEM_FLOATS) ? s_field[rm2] : __ldg(field + rm2);
        float f3 = (rm3 < SMEM_FLOATS) ? s_field[rm3] : __ldg(field + rm3);

        atomicAdd(out + (unsigned)r.x, v.x * f0);
        atomicAdd(out + (unsigned)r.y, v.y * f1);
        atomicAdd(out + (unsigned)r.z, v.z * f2);
        atomicAdd(out + (unsigned)r.w, v.w * f3);
    }

    // Tail (nnz % 4) — defensive
    long long tail_start = nvec << 2;
    for (long long i = tail_start + tid; i < nnz; i += stride) {
        unsigned cc = (unsigned)__ldcs(idx_col + i);
        unsigned rm = ((cc & 255u) << 8) | (cc >> 8);
        float f = (rm < SMEM_FLOATS) ? s_field[rm] : __ldg(field + rm);
        atomicAdd(out + (unsigned)__ldcs(idx_row + i), __ldcs(vals + i) * f);
    }
}

extern "C" void kernel_launch(void* const* d_in, const int* in_sizes, int n_in,
                              void* d_out, int out_size)
{
    const float* field   = (const float*)d_in[0];
    const int*   idx_row = (const int*)d_in[1];
    const int*   idx_col = (const int*)d_in[2];
    const float* vals    = (const float*)d_in[3];
    float* out = (float*)d_out;
    long long nnz = (long long)in_sizes[1];

    {
        int threads = 256;
        int blocks = (out_size + threads - 1) / threads;
        zero_out_kernel<<<blocks, threads>>>(out, out_size);
    }
    {
        int nsm = 148;  // B300 default; query clamps to actual (152 on GB300)
        int dev = 0;
        if (cudaGetDevice(&dev) == cudaSuccess) {
            int q = 0;
            if (cudaDeviceGetAttribute(&q, cudaDevAttrMultiProcessorCount, dev) == cudaSuccess && q > 0)
                nsm = q;
        }
        cudaFuncSetAttribute(spmv_smem_kernel,
                             cudaFuncAttributeMaxDynamicSharedMemorySize, SMEM_BYTES);
        spmv_smem_kernel<<<nsm, 1024, SMEM_BYTES>>>(field, idx_row, idx_col, vals, out, nnz);
    }
}

// round 6
// speedup vs baseline: 1.3135x; 1.0020x over previous
#include <cuda_runtime.h>
#include <cstdint>

// out[idx_row[i]] += vals[i] * field[rm(idx_col[i])],  rm(c) = ((c&255)<<8)|(c>>8)
// 227KB of field (fp32) in SMEM; software-pipelined streaming loads (prefetch
// next grid-stride iteration) to hide DRAM latency at 32 warps/SM.

#define SMEM_BYTES  232448           // 227 KB
#define SMEM_FLOATS (SMEM_BYTES / 4) // 58112

__global__ void zero_out_kernel(float* __restrict__ out, int n) {
    int i = blockIdx.x * blockDim.x + threadIdx.x;
    if (i < n) out[i] = 0.0f;
}

__global__ void __launch_bounds__(1024, 1)
spmv_smem_kernel(const float* __restrict__ field,
                 const int*   __restrict__ idx_row,
                 const int*   __restrict__ idx_col,
                 const float* __restrict__ vals,
                 float*       __restrict__ out,
                 long long nnz)
{
    extern __shared__ float s_field[];

    {   // coalesced row-major fill of field[0:SMEM_FLOATS]
        const float4* f4 = reinterpret_cast<const float4*>(field);
        float4* s4 = reinterpret_cast<float4*>(s_field);
        for (int i = threadIdx.x; i < SMEM_FLOATS / 4; i += blockDim.x)
            s4[i] = f4[i];
    }
    __syncthreads();

    const int4*   col4 = reinterpret_cast<const int4*>(idx_col);
    const int4*   row4 = reinterpret_cast<const int4*>(idx_row);
    const float4* val4 = reinterpret_cast<const float4*>(vals);

    long long tid    = (long long)blockIdx.x * blockDim.x + threadIdx.x;
    long long stride = (long long)gridDim.x * blockDim.x;
    long long nvec   = nnz >> 2;

    long long g = tid;
    int4 c, r; float4 v;
    if (g < nvec) {
        c = __ldcs(col4 + g);
        r = __ldcs(row4 + g);
        v = __ldcs(val4 + g);
    }

    while (g < nvec) {
        long long gn = g + stride;
        int4 cn, rn; float4 vn;
        if (gn < nvec) {            // prefetch next iteration's streams
            cn = __ldcs(col4 + gn);
            rn = __ldcs(row4 + gn);
            vn = __ldcs(val4 + gn);
        }

        unsigned rm0 = (((unsigned)c.x & 255u) << 8) | ((unsigned)c.x >> 8);
        unsigned rm1 = (((unsigned)c.y & 255u) << 8) | ((unsigned)c.y >> 8);
        unsigned rm2 = (((unsigned)c.z & 255u) << 8) | ((unsigned)c.z >> 8);
        unsigned rm3 = (((unsigned)c.w & 255u) << 8) | ((unsigned)c.w >> 8);

        float f0 = (rm0 < SMEM_FLOATS) ? s_field[rm0] : __ldg(field + rm0);
        float f1 = (rm1 < SMEM_FLOATS) ? s_field[rm1] : __ldg(field + rm1);
        float f2 = (rm2 < SMEM_FLOATS) ? s_field[rm2] : __ldg(field + rm2);
        float f3 = (rm3 < SMEM_FLOATS) ? s_field[rm3] : __ldg(field + rm3);

        atomicAdd(out + (unsigned)r.x, v.x * f0);
        atomicAdd(out + (unsigned)r.y, v.y * f1);
        atomicAdd(out + (unsigned)r.z, v.z * f2);
        atomicAdd(out + (unsigned)r.w, v.w * f3);

        c = cn; r = rn; v = vn;
        g = gn;
    }

    // tail (nnz % 4) — defensive
    long long tail_start = nvec << 2;
    for (long long i = tail_start + tid; i < nnz; i += stride) {
        unsigned cc = (unsigned)__ldcs(idx_col + i);
        unsigned rm = ((cc & 255u) << 8) | (cc >> 8);
        float f = (rm < SMEM_FLOATS) ? s_field[rm] : __ldg(field + rm);
        atomicAdd(out + (unsigned)__ldcs(idx_row + i), __ldcs(vals + i) * f);
    }
}

extern "C" void kernel_launch(void* const* d_in, const int* in_sizes, int n_in,
                              void* d_out, int out_size)
{
    const float* field   = (const float*)d_in[0];
    const int*   idx_row = (const int*)d_in[1];
    const int*   idx_col = (const int*)d_in[2];
    const float* vals    = (const float*)d_in[3];
    float* out = (float*)d_out;
    long long nnz = (long long)in_sizes[1];

    {
        int threads = 256;
        int blocks = (out_size + threads - 1) / threads;
        zero_out_kernel<<<blocks, threads>>>(out, out_size);
    }
    {
        int nsm = 148;
        int dev = 0;
        if (cudaGetDevice(&dev) == cudaSuccess) {
            int q = 0;
            if (cudaDeviceGetAttribute(&q, cudaDevAttrMultiProcessorCount, dev) == cudaSuccess && q > 0)
                nsm = q;
        }
        cudaFuncSetAttribute(spmv_smem_kernel,
                             cudaFuncAttributeMaxDynamicSharedMemorySize, SMEM_BYTES);
        spmv_smem_kernel<<<nsm, 1024, SMEM_BYTES>>>(field, idx_row, idx_col, vals, out, nnz);
    }
}

// round 7
// speedup vs baseline: 1.3526x; 1.0298x over previous
#include <cuda_runtime.h>
#include <cuda_fp16.h>
#include <cstdint>

// out[idx_row[i]] += vals[i] * field[rm(idx_col[i])],  rm(c) = ((c&255)<<8)|(c>>8)
// Entire 65536-elem field stored in SMEM as fp16 (128KB) -> every gather is an
// LDS (no divergent L1tex fallback). Scatter = 30M REDG.ADD.F32 (LSU floor).

#define FIELD_ELEMS 65536
#define SMEM_BYTES  (FIELD_ELEMS * 2)   // 128 KB

__global__ void zero_out_kernel(float* __restrict__ out, int n) {
    int i = blockIdx.x * blockDim.x + threadIdx.x;
    if (i < n) out[i] = 0.0f;
}

__global__ void __launch_bounds__(1024, 1)
spmv_smem_kernel(const float* __restrict__ field,
                 const int*   __restrict__ idx_row,
                 const int*   __restrict__ idx_col,
                 const float* __restrict__ vals,
                 float*       __restrict__ out,
                 long long nnz)
{
    extern __shared__ __half s_field[];

    // Coalesced fill with fp32 -> fp16 convert (row-major original layout).
    {
        const float4* f4 = reinterpret_cast<const float4*>(field);
        for (int i = threadIdx.x; i < FIELD_ELEMS / 4; i += blockDim.x) {
            float4 f = f4[i];
            __half2 h0 = __floats2half2_rn(f.x, f.y);
            __half2 h1 = __floats2half2_rn(f.z, f.w);
            reinterpret_cast<__half2*>(s_field)[2 * i]     = h0;
            reinterpret_cast<__half2*>(s_field)[2 * i + 1] = h1;
        }
    }
    __syncthreads();

    const int4*   col4 = reinterpret_cast<const int4*>(idx_col);
    const int4*   row4 = reinterpret_cast<const int4*>(idx_row);
    const float4* val4 = reinterpret_cast<const float4*>(vals);

    long long tid    = (long long)blockIdx.x * blockDim.x + threadIdx.x;
    long long stride = (long long)gridDim.x * blockDim.x;
    long long nvec   = nnz >> 2;

    for (long long g = tid; g < nvec; g += stride) {
        int4   c = __ldcs(col4 + g);
        int4   r = __ldcs(row4 + g);
        float4 v = __ldcs(val4 + g);

        unsigned rm0 = (((unsigned)c.x & 255u) << 8) | ((unsigned)c.x >> 8);
        unsigned rm1 = (((unsigned)c.y & 255u) << 8) | ((unsigned)c.y >> 8);
        unsigned rm2 = (((unsigned)c.z & 255u) << 8) | ((unsigned)c.z >> 8);
        unsigned rm3 = (((unsigned)c.w & 255u) << 8) | ((unsigned)c.w >> 8);

        float f0 = __half2float(s_field[rm0]);
        float f1 = __half2float(s_field[rm1]);
        float f2 = __half2float(s_field[rm2]);
        float f3 = __half2float(s_field[rm3]);

        atomicAdd(out + (unsigned)r.x, v.x * f0);
        atomicAdd(out + (unsigned)r.y, v.y * f1);
        atomicAdd(out + (unsigned)r.z, v.z * f2);
        atomicAdd(out + (unsigned)r.w, v.w * f3);
    }

    // tail (nnz % 4) — defensive
    long long tail_start = nvec << 2;
    for (long long i = tail_start + tid; i < nnz; i += stride) {
        unsigned cc = (unsigned)__ldcs(idx_col + i);
        unsigned rm = ((cc & 255u) << 8) | (cc >> 8);
        float f = __half2float(s_field[rm]);
        atomicAdd(out + (unsigned)__ldcs(idx_row + i), __ldcs(vals + i) * f);
    }
}

extern "C" void kernel_launch(void* const* d_in, const int* in_sizes, int n_in,
                              void* d_out, int out_size)
{
    const float* field   = (const float*)d_in[0];
    const int*   idx_row = (const int*)d_in[1];
    const int*   idx_col = (const int*)d_in[2];
    const float* vals    = (const float*)d_in[3];
    float* out = (float*)d_out;
    long long nnz = (long long)in_sizes[1];

    {
        int threads = 256;
        int blocks = (out_size + threads - 1) / threads;
        zero_out_kernel<<<blocks, threads>>>(out, out_size);
    }
    {
        int nsm = 148;
        int dev = 0;
        if (cudaGetDevice(&dev) == cudaSuccess) {
            int q = 0;
            if (cudaDeviceGetAttribute(&q, cudaDevAttrMultiProcessorCount, dev) == cudaSuccess && q > 0)
                nsm = q;
        }
        cudaFuncSetAttribute(spmv_smem_kernel,
                             cudaFuncAttributeMaxDynamicSharedMemorySize, SMEM_BYTES);
        spmv_smem_kernel<<<nsm, 1024, SMEM_BYTES>>>(field, idx_row, idx_col, vals, out, nnz);
    }
}